// round 15
// baseline (speedup 1.0000x reference)
#include <cuda_runtime.h>

#define MEM_M 131072
#define E 512
#define CHROWS 4
#define NCHUNK (MEM_M / CHROWS)
#define GRID 296
#define NTHR 256

typedef unsigned long long u64;

// ---- device scratch (no allocation allowed) ----
// Double-buffered by replay parity: each launch zeroes the other parity's
// buffers, so every launch sees zeroed accumulators deterministically.
__device__ __align__(16) float g_keys[2][3 * E];  // [par][m*E+j] m:0=w,1=r,2=erase
__device__ __align__(16) float g_acc[2][2 * E];   // [par][0..E)=accA, [E..2E)=accB
__device__ float g_Spair[2][2];                   // [par][0]=S_r, [1]=S_w
__device__ unsigned g_nextc[2];                   // [par] work-steal counter
__device__ unsigned g_count;                      // barrier ticket (self-resets)
__device__ unsigned g_flag;                       // barrier epoch (monotonic)

// ---- packed f32x2 helpers (sm_103a native FFMA2) ----
__device__ __forceinline__ u64 pk2(float lo, float hi) {
    u64 r; asm("mov.b64 %0, {%1, %2};" : "=l"(r) : "f"(lo), "f"(hi)); return r;
}
__device__ __forceinline__ float hadd2(u64 v) {
    float lo, hi; asm("mov.b64 {%0, %1}, %2;" : "=f"(lo), "=f"(hi) : "l"(v));
    return lo + hi;
}
__device__ __forceinline__ u64 fma2(u64 a, u64 b, u64 c) {
    u64 r; asm("fma.rn.f32x2 %0, %1, %2, %3;" : "=l"(r) : "l"(a), "l"(b), "l"(c));
    return r;
}

// grid-wide barrier: all GRID blocks co-resident (296 = 2*148 CTAs at
// __launch_bounds__(256,2)).
__device__ __forceinline__ void gbar(unsigned target) {
    __syncthreads();
    if (threadIdx.x == 0) {
        __threadfence();
        unsigned t = atomicAdd(&g_count, 1u);
        if (t == GRID - 1) {
            g_count = 0u;
            __threadfence();
            atomicExch(&g_flag, target);
        } else {
            while (*(volatile unsigned*)&g_flag < target) __nanosleep(64);
        }
        __threadfence();
    }
    __syncthreads();
}

#define PROCESS_ROW(V) do {                                                     \
    u64 dr2 = 0ull, dw2 = 0ull, nn2 = 0ull;                                     \
    _Pragma("unroll")                                                           \
    for (int i = 0; i < 8; i++) {                                               \
        dr2 = fma2(V[i], kr[i], dr2);                                           \
        dw2 = fma2(V[i], kw[i], dw2);                                           \
        nn2 = fma2(V[i], V[i], nn2);                                            \
    }                                                                           \
    float dr = hadd2(dr2), dw = hadd2(dw2), nn = hadd2(nn2);                    \
    _Pragma("unroll")                                                           \
    for (int o = 16; o; o >>= 1) {                                              \
        dr += __shfl_xor_sync(0xffffffffu, dr, o);                              \
        dw += __shfl_xor_sync(0xffffffffu, dw, o);                              \
        nn += __shfl_xor_sync(0xffffffffu, nn, o);                              \
    }                                                                           \
    const float inv = rsqrtf(nn);                                               \
    const float sr = dr * inv;                                                  \
    const float sw = dw * inv;                                                  \
    const float srw = sr * sw;                                                  \
    const u64 sr2 = pk2(sr, sr), srw2 = pk2(srw, srw);                          \
    _Pragma("unroll")                                                           \
    for (int i = 0; i < 8; i++) {                                               \
        acA[i] = fma2(V[i], sr2, acA[i]);                                       \
        acB[i] = fma2(V[i], srw2, acB[i]);                                      \
    }                                                                           \
    Sr += sr; Sw += sw;                                                         \
} while (0)

#define LOAD_ROW(D, rowptr) do {                                                \
    _Pragma("unroll")                                                           \
    for (int q = 0; q < 4; q++) {                                               \
        float4 t = __ldcs((rowptr) + q * 32);                                   \
        D[2 * q]     = ((u64*)&t)[0];                                           \
        D[2 * q + 1] = ((u64*)&t)[1];                                           \
    }                                                                           \
} while (0)

__global__ void __launch_bounds__(NTHR, 2) k_fused(
        const float* __restrict__ mem,
        const float* __restrict__ x,
        const float* __restrict__ wkg,
        const float* __restrict__ weg,
        const float* __restrict__ rkg,
        const float* __restrict__ post,
        float* __restrict__ out) {
    __shared__ u64 shA[8][256];   // 16 KB
    __shared__ u64 shB[8][256];   // 16 KB
    __shared__ float sS[16];
    __shared__ float sx[8];
    __shared__ float sc[4];
    __shared__ unsigned sflag;

    const int b = blockIdx.x, tid = threadIdx.x;
    const int w = tid >> 5, l = tid & 31;

    // entry epoch (read before ANY block can release barrier 1 -> race-free)
    if (tid == 0) sflag = *(volatile unsigned*)&g_flag;
    __syncthreads();
    const unsigned flag0 = sflag;
    const int par = (int)((flag0 >> 1) & 1u);

    // ======== Phase A: key GEMVs, 192 blocks (3 mats x 64 chunks) ========
    if (b < 192) {
        const int m = b >> 6, p = b & 63;   // matrix, 8-row chunk
        const float* W = (m == 0) ? wkg : ((m == 1) ? rkg : weg);
        if (tid < 8) sx[tid] = x[p * 8 + tid];
        __syncthreads();
        float a0 = 0.f, a1 = 0.f;
#pragma unroll
        for (int i = 0; i < 8; i++) {
            const float* row = W + (p * 8 + i) * E;
            a0 += sx[i] * row[tid];
            a1 += sx[i] * row[tid + 256];
        }
        atomicAdd(&g_keys[par][m * E + tid], a0);
        atomicAdd(&g_keys[par][m * E + tid + 256], a1);
    } else if (b == 192) {
        const int op = 1 - par;   // zero other-parity buffers for next launch
        for (int j = tid; j < 3 * E; j += NTHR) g_keys[op][j] = 0.f;
        for (int j = tid; j < 2 * E; j += NTHR) g_acc[op][j] = 0.f;
        if (tid < 2) g_Spair[op][tid] = 0.f;
        if (tid == 0) g_nextc[op] = 0u;
        out[tid] = 0.f;
        out[tid + 256] = 0.f;
    }

    gbar(flag0 + 1);

    // ================= Phase B: main pass (work-stealing) =================
    u64 kr[8], kw[8];
    {
        const u64* rk = (const u64*)(g_keys[par] + E);   // m=1 r_key
        const u64* wk = (const u64*)(g_keys[par]);       // m=0 w_key
#pragma unroll
        for (int q = 0; q < 4; q++) {
            kr[2 * q]     = rk[(q * 32 + l) * 2];
            kr[2 * q + 1] = rk[(q * 32 + l) * 2 + 1];
            kw[2 * q]     = wk[(q * 32 + l) * 2];
            kw[2 * q + 1] = wk[(q * 32 + l) * 2 + 1];
        }
    }

    u64 acA[8], acB[8];
#pragma unroll
    for (int i = 0; i < 8; i++) { acA[i] = 0ull; acB[i] = 0ull; }
    float Sr = 0.f, Sw = 0.f;

    unsigned* nextc = &g_nextc[par];
    unsigned c0 = 0, c1 = 0;
    if (l == 0) c0 = atomicAdd(nextc, 1u);
    c0 = __shfl_sync(0xffffffffu, c0, 0);
    if (l == 0) c1 = atomicAdd(nextc, 1u);
    c1 = __shfl_sync(0xffffffffu, c1, 0);

    u64 v[8], p[8];
    while (c0 < NCHUNK) {
        const float4* base = (const float4*)mem + (size_t)c0 * CHROWS * 128 + l;
        LOAD_ROW(v, base);
#pragma unroll
        for (int r = 0; r < CHROWS; r++) {
            if (r < CHROWS - 1) {
                LOAD_ROW(p, base + (r + 1) * 128);
            } else if (c1 < NCHUNK) {
                const float4* nb = (const float4*)mem + (size_t)c1 * CHROWS * 128 + l;
                LOAD_ROW(p, nb);
            }
            PROCESS_ROW(v);
#pragma unroll
            for (int i = 0; i < 8; i++) v[i] = p[i];
        }
        c0 = c1;
        if (l == 0) c1 = atomicAdd(nextc, 1u);   // one chunk ahead
        c1 = __shfl_sync(0xffffffffu, c1, 0);
    }

    // block-level reduce -> global atomics
#pragma unroll
    for (int q = 0; q < 4; q++) {
        shA[w][(q * 32 + l) * 2]     = acA[2 * q];
        shA[w][(q * 32 + l) * 2 + 1] = acA[2 * q + 1];
        shB[w][(q * 32 + l) * 2]     = acB[2 * q];
        shB[w][(q * 32 + l) * 2 + 1] = acB[2 * q + 1];
    }
    if (l == 0) { sS[w] = Sr; sS[8 + w] = Sw; }
    __syncthreads();

    {
        const float* fA = (const float*)shA;
        const float* fB = (const float*)shB;
        for (int j = tid; j < E; j += NTHR) {
            float a = 0.f, bb = 0.f;
#pragma unroll
            for (int k = 0; k < 8; k++) {
                a  += fA[k * E + j];
                bb += fB[k * E + j];
            }
            atomicAdd(&g_acc[par][j], a);
            atomicAdd(&g_acc[par][E + j], bb);
        }
        if (tid == 0) {
            float r = 0.f, ww = 0.f;
#pragma unroll
            for (int k = 0; k < 8; k++) { r += sS[k]; ww += sS[8 + k]; }
            atomicAdd(&g_Spair[par][0], r);
            atomicAdd(&g_Spair[par][1], ww);
        }
    }

    gbar(flag0 + 2);

    // ================= Phase C: output GEMV =================
    if (b < 256) {
        const int i0 = b * 4;
        if (tid < 4) {
            const int i = i0 + tid;
            float ci;
            if (i < E) {
                ci = x[i];
            } else {
                const int e = i - E;
                ci = (g_acc[par][e] -
                      g_keys[par][2 * E + e] * g_acc[par][E + e] *
                          __frcp_rn(g_Spair[par][1])) *
                     __frcp_rn(g_Spair[par][0]);
            }
            sc[tid] = ci;
        }
        __syncthreads();
        float a0 = 0.f, a1 = 0.f;
#pragma unroll
        for (int i = 0; i < 4; i++) {
            const float* row = post + (size_t)(i0 + i) * E;
            a0 += sc[i] * row[tid];
            a1 += sc[i] * row[tid + 256];
        }
        atomicAdd(&out[tid], a0);
        atomicAdd(&out[tid + 256], a1);
    }
}

// ============================================================
extern "C" void kernel_launch(void* const* d_in, const int* in_sizes, int n_in,
                              void* d_out, int out_size) {
    const float* x    = (const float*)d_in[0];
    const float* mem  = (const float*)d_in[1];
    const float* wkg  = (const float*)d_in[2];
    // d_in[3] = w_vect_gen: computed-but-unused in the reference (dead)
    const float* weg  = (const float*)d_in[4];
    const float* rkg  = (const float*)d_in[5];
    const float* post = (const float*)d_in[6];

    k_fused<<<GRID, NTHR>>>(mem, x, wkg, weg, rkg, post, (float*)d_out);
}

// round 17
// speedup vs baseline: 1.0654x; 1.0654x over previous
#include <cuda_runtime.h>

#define MEM_M 131072
#define E 512
#define CHROWS 4
#define NCHUNK (MEM_M / CHROWS)

typedef unsigned long long u64;

// ---- device scratch (no allocation allowed) ----
// key GEMV partials: [m][p][E], m: 0=w_key, 1=r_key, 2=erase ; p = 8 chunks
__device__ __align__(16) float g_kpart[3 * 8 * E];
__device__ __align__(16) float g_accA[E];             // sum sims_r * mem
__device__ __align__(16) float g_accB[E];             // sum sims_r * sims_w * mem
__device__ float g_S[2];                              // S_r, S_w
__device__ unsigned g_next;                           // work-stealing counter
__device__ float g_sink;                              // defeats DCE in prefetch

// ---- packed f32x2 helpers (sm_103a native FFMA2) ----
__device__ __forceinline__ u64 pk2(float lo, float hi) {
    u64 r; asm("mov.b64 %0, {%1, %2};" : "=l"(r) : "f"(lo), "f"(hi)); return r;
}
__device__ __forceinline__ float hadd2(u64 v) {
    float lo, hi; asm("mov.b64 {%0, %1}, %2;" : "=f"(lo), "=f"(hi) : "l"(v));
    return lo + hi;
}
__device__ __forceinline__ u64 fma2(u64 a, u64 b, u64 c) {
    u64 r; asm("fma.rn.f32x2 %0, %1, %2, %3;" : "=l"(r) : "l"(a), "l"(b), "l"(c));
    return r;
}

// ============================================================
// K1 k_prep:
//  blocks 0..23 : key GEMV partials (m = b>>3, chunk p = b&7, 64 rows)
//                 (UNNORMALIZED keys: 1/||key|| cancels in sims/sum)
//  block 24     : zero accumulators / counter / out
//  blocks 25..56: prefetch `post` (2 MB) into L2 so k_out hits L2
//                 even after k_main's 256 MB evict-first stream.
// ============================================================
__global__ void k_prep(const float* __restrict__ x,
                       const float* __restrict__ wkg,
                       const float* __restrict__ weg,
                       const float* __restrict__ rkg,
                       const float* __restrict__ post,
                       float* __restrict__ out) {
    const int b = blockIdx.x, j = threadIdx.x;
    if (b == 24) {
        g_accA[j] = 0.f;
        g_accB[j] = 0.f;
        out[j] = 0.f;
        if (j < 2) g_S[j] = 0.f;
        if (j == 0) g_next = 0u;
        return;
    }
    if (b >= 25) {
        // prefetch post: 32 blocks x 512 threads x 8 float4 = 2 MB
        const int pb = b - 25;
        const float4* p4 = (const float4*)post + (size_t)pb * 4096 + j;
        float s = 0.f;
#pragma unroll
        for (int q = 0; q < 8; q++) {
            float4 t = p4[q * 512];
            s += t.x + t.y + t.z + t.w;
        }
        if (s == 1.234567e30f) g_sink = s;   // never true; keeps loads live
        return;
    }
    const int m = b >> 3, p = b & 7;
    const float* W = (m == 0) ? wkg : ((m == 1) ? rkg : weg);
    __shared__ float sx[64];
    if (j < 64) sx[j] = x[p * 64 + j];
    __syncthreads();
    float acc = 0.f;
#pragma unroll 8
    for (int i = 0; i < 64; i++)
        acc += sx[i] * W[(p * 64 + i) * E + j];
    g_kpart[(m * 8 + p) * E + j] = acc;
}

// ============================================================
// K2 k_main: single pass over memory (256 MB), work-stealing.
// One warp processes 4-row contiguous chunks grabbed from g_next.
// Prologue reduces key partials from L2 into shared -> registers.
// Heavy math in packed f32x2 (FFMA2).   [UNCHANGED — protected]
// ============================================================
#define PROCESS_ROW(V) do {                                                     \
    u64 dr2 = 0ull, dw2 = 0ull, nn2 = 0ull;                                     \
    _Pragma("unroll")                                                           \
    for (int i = 0; i < 8; i++) {                                               \
        dr2 = fma2(V[i], kr[i], dr2);                                           \
        dw2 = fma2(V[i], kw[i], dw2);                                           \
        nn2 = fma2(V[i], V[i], nn2);                                            \
    }                                                                           \
    float dr = hadd2(dr2), dw = hadd2(dw2), nn = hadd2(nn2);                    \
    _Pragma("unroll")                                                           \
    for (int o = 16; o; o >>= 1) {                                              \
        dr += __shfl_xor_sync(0xffffffffu, dr, o);                              \
        dw += __shfl_xor_sync(0xffffffffu, dw, o);                              \
        nn += __shfl_xor_sync(0xffffffffu, nn, o);                              \
    }                                                                           \
    const float inv = rsqrtf(nn);                                               \
    const float sr = dr * inv;                                                  \
    const float sw = dw * inv;                                                  \
    const float srw = sr * sw;                                                  \
    const u64 sr2 = pk2(sr, sr), srw2 = pk2(srw, srw);                          \
    _Pragma("unroll")                                                           \
    for (int i = 0; i < 8; i++) {                                               \
        acA[i] = fma2(V[i], sr2, acA[i]);                                       \
        acB[i] = fma2(V[i], srw2, acB[i]);                                      \
    }                                                                           \
    Sr += sr; Sw += sw;                                                         \
} while (0)

#define LOAD_ROW(D, rowptr) do {                                                \
    _Pragma("unroll")                                                           \
    for (int q = 0; q < 4; q++) {                                               \
        float4 t = __ldcs((rowptr) + q * 32);                                   \
        D[2 * q]     = ((u64*)&t)[0];                                           \
        D[2 * q + 1] = ((u64*)&t)[1];                                           \
    }                                                                           \
} while (0)

__global__ void __launch_bounds__(256, 2) k_main(const float* __restrict__ mem) {
    __shared__ u64 shA[8][256];   // 16 KB
    __shared__ u64 shB[8][256];   // 16 KB
    __shared__ float skey[2 * E]; // [0..511] = r_key, [512..1023] = w_key
    __shared__ float sS[16];

    const int tid = threadIdx.x;
    const int w = tid >> 5, l = tid & 31;

    // ---- prologue: reduce key partials (8 each) from L2 ----
    {
        const int which = tid >> 7;           // 0 -> r_key (m=1), 1 -> w_key (m=0)
        const int col = tid & 127;            // float4 column
        const int m = which ? 0 : 1;
        const float4* kp4 = (const float4*)g_kpart;
        float4 s = make_float4(0, 0, 0, 0);
#pragma unroll
        for (int p = 0; p < 8; p++) {
            float4 v = kp4[(m * 8 + p) * 128 + col];
            s.x += v.x; s.y += v.y; s.z += v.z; s.w += v.w;
        }
        ((float4*)skey)[which * 128 + col] = s;
    }
    __syncthreads();

    u64 kr[8], kw[8];
    {
        const u64* rk = (const u64*)skey;
        const u64* wk = (const u64*)(skey + E);
#pragma unroll
        for (int q = 0; q < 4; q++) {
            kr[2 * q]     = rk[(q * 32 + l) * 2];
            kr[2 * q + 1] = rk[(q * 32 + l) * 2 + 1];
            kw[2 * q]     = wk[(q * 32 + l) * 2];
            kw[2 * q + 1] = wk[(q * 32 + l) * 2 + 1];
        }
    }

    u64 acA[8], acB[8];
#pragma unroll
    for (int i = 0; i < 8; i++) { acA[i] = 0ull; acB[i] = 0ull; }
    float Sr = 0.f, Sw = 0.f;

    // ---- work-stealing mainloop: 4-row contiguous chunks ----
    unsigned c0 = 0, c1 = 0;
    if (l == 0) c0 = atomicAdd(&g_next, 1u);
    c0 = __shfl_sync(0xffffffffu, c0, 0);
    if (l == 0) c1 = atomicAdd(&g_next, 1u);
    c1 = __shfl_sync(0xffffffffu, c1, 0);

    u64 v[8], p[8];

    while (c0 < NCHUNK) {
        const float4* base = (const float4*)mem + (size_t)c0 * CHROWS * 128 + l;
        LOAD_ROW(v, base);
#pragma unroll
        for (int r = 0; r < CHROWS; r++) {
            if (r < CHROWS - 1) {
                LOAD_ROW(p, base + (r + 1) * 128);
            } else if (c1 < NCHUNK) {
                const float4* nb = (const float4*)mem + (size_t)c1 * CHROWS * 128 + l;
                LOAD_ROW(p, nb);
            }
            PROCESS_ROW(v);
#pragma unroll
            for (int i = 0; i < 8; i++) v[i] = p[i];
        }
        c0 = c1;
        if (l == 0) c1 = atomicAdd(&g_next, 1u);   // one chunk ahead
        c1 = __shfl_sync(0xffffffffu, c1, 0);
    }

    // per-warp accumulators -> shared slices (same packed layout)
#pragma unroll
    for (int q = 0; q < 4; q++) {
        shA[w][(q * 32 + l) * 2]     = acA[2 * q];
        shA[w][(q * 32 + l) * 2 + 1] = acA[2 * q + 1];
        shB[w][(q * 32 + l) * 2]     = acB[2 * q];
        shB[w][(q * 32 + l) * 2 + 1] = acB[2 * q + 1];
    }
    if (l == 0) { sS[w] = Sr; sS[8 + w] = Sw; }
    __syncthreads();

    const float* fA = (const float*)shA;
    const float* fB = (const float*)shB;
    for (int j = tid; j < E; j += 256) {
        float a = 0.f, b = 0.f;
#pragma unroll
        for (int k = 0; k < 8; k++) {
            a += fA[k * E + j];
            b += fB[k * E + j];
        }
        atomicAdd(&g_accA[j], a);
        atomicAdd(&g_accB[j], b);
    }
    if (tid == 0) {
        float r = 0.f, ww = 0.f;
#pragma unroll
        for (int k = 0; k < 8; k++) { r += sS[k]; ww += sS[8 + k]; }
        atomicAdd(&g_S[0], r);
        atomicAdd(&g_S[1], ww);
    }
}

// ============================================================
// K3 k_out: output GEMV (shared coefs, scalar coalesced loads),
// atomics into d_out (zeroed by prep).  post should be L2-hot
// thanks to k_prep's prefetch blocks.
// 128 blocks; block b handles rows [8b, 8b+8).
// ============================================================
__global__ void k_out(const float* __restrict__ x,
                      const float* __restrict__ post,
                      float* __restrict__ out) {
    __shared__ float sc[8];
    const int b = blockIdx.x, t = threadIdx.x;
    const int i0 = b * 8;
    if (t < 8) {
        const int i = i0 + t;
        float ci;
        if (i < E) {
            ci = x[i];
        } else {
            const int e = i - E;
            float er = 0.f;
#pragma unroll
            for (int p = 0; p < 8; p++) er += g_kpart[(16 + p) * E + e];
            ci = (g_accA[e] - er * g_accB[e] * __frcp_rn(g_S[1])) * __frcp_rn(g_S[0]);
        }
        sc[t] = ci;
    }
    __syncthreads();
#pragma unroll
    for (int jj = 0; jj < 2; jj++) {
        const int j = t + jj * 256;
        float acc = 0.f;
#pragma unroll
        for (int i = 0; i < 8; i++)
            acc += sc[i] * post[(i0 + i) * E + j];
        atomicAdd(&out[j], acc);
    }
}

// ============================================================
extern "C" void kernel_launch(void* const* d_in, const int* in_sizes, int n_in,
                              void* d_out, int out_size) {
    const float* x    = (const float*)d_in[0];
    const float* mem  = (const float*)d_in[1];
    const float* wkg  = (const float*)d_in[2];
    // d_in[3] = w_vect_gen: computed-but-unused in the reference (dead)
    const float* weg  = (const float*)d_in[4];
    const float* rkg  = (const float*)d_in[5];
    const float* post = (const float*)d_in[6];
    float* out = (float*)d_out;

    k_prep<<<57, 512>>>(x, wkg, weg, rkg, post, out);
    k_main<<<296, 256>>>(mem);
    k_out<<<128, 256>>>(x, post, out);
}